// round 1
// baseline (speedup 1.0000x reference)
#include <cuda_runtime.h>
#include <math.h>
#include <float.h>

#define MAXB 16
#define MAXA 33600
#define MAXT 50
#define TPAD 56
#define NCLS 80
#define KCAND 10

// Scratch (static __device__ globals per harness rules; ~142MB total)
__device__ int    d_cnt[MAXB];
__device__ float4 d_gbox [MAXB][MAXA];
__device__ float4 d_gmeta[MAXB][MAXA];
__device__ float  d_gct  [MAXB][MAXA][TPAD];
__device__ int    d_bestt[MAXB * MAXA];
__device__ float  d_piou [MAXB * MAXA];
__device__ int    d_count[MAXB * MAXA];
__device__ int    d_mint [MAXB * MAXA];

__global__ void k0_zero() {
    if (threadIdx.x < MAXB) d_cnt[threadIdx.x] = 0;
}

// K1: per-anchor pass. Computes S (softplus sum), best_t (argmin cost over t),
// p_iou (max iou over t), in_box_anchor; compacts good anchors with
// precomputed cls-cost rows.
__global__ __launch_bounds__(128) void k1_anchor(
    const float* __restrict__ pred, const float* __restrict__ target,
    const float* __restrict__ grid, const float* __restrict__ stridem,
    int A, int T)
{
    __shared__ float sp[128 * 85];          // padded pred rows (85 coprime w/ 32 banks)
    __shared__ float st[MAXT * 8];          // x0,y0,x1,y1,cx,cy,area,(pad)
    __shared__ int   scls[MAXT];

    int b    = blockIdx.y;
    int base = blockIdx.x * 128;
    int nrows = min(128, A - base);

    const float* predb = pred + ((size_t)b * A + base) * 84;
    for (int i = threadIdx.x; i < nrows * 84; i += 128) {
        int r = i / 84;
        int c = i - r * 84;
        sp[r * 85 + c] = predb[i];
    }
    for (int i = threadIdx.x; i < T; i += 128) {
        const float* tg = target + ((size_t)b * T + i) * 5;
        float cl = tg[0], x0 = tg[1], y0 = tg[2], x1 = tg[3], y1 = tg[4];
        st[i * 8 + 0] = x0; st[i * 8 + 1] = y0;
        st[i * 8 + 2] = x1; st[i * 8 + 3] = y1;
        st[i * 8 + 4] = 0.5f * (x0 + x1);
        st[i * 8 + 5] = 0.5f * (y0 + y1);
        st[i * 8 + 6] = (x1 - x0) * (y1 - y0);
        scls[i] = (int)cl;
    }
    __syncthreads();

    int tid  = threadIdx.x;
    int lane = tid & 31;
    bool alive = (tid < nrows);
    int a = base + tid;

    bool iba = false;
    float S = 0.f, px0 = 0, py0 = 0, px1 = 0, py1 = 0, xc = 0, yc = 0, rad = 0;
    const float* row = sp + tid * 85;

    if (alive) {
        float strv = stridem[a];
        xc  = (grid[2 * a]     + 0.5f) * strv;
        yc  = (grid[2 * a + 1] + 0.5f) * strv;
        rad = 2.5f * strv;
        px0 = row[0]; py0 = row[1]; px1 = row[2]; py1 = row[3];
        float areaP = (px1 - px0) * (py1 - py0);

        #pragma unroll 8
        for (int c = 0; c < NCLS; c++) {
            float z = row[4 + c];
            S += fmaxf(z, 0.f) + log1pf(expf(-fabsf(z)));   // stable softplus
        }

        bool anyB = false, anyC = false;
        float bestC = FLT_MAX;
        int   bestT = 0;
        float maxiou = 0.f;

        for (int t = 0; t < T; t++) {
            float tx0 = st[t * 8 + 0], ty0 = st[t * 8 + 1];
            float tx1 = st[t * 8 + 2], ty1 = st[t * 8 + 3];
            float cxt = st[t * 8 + 4], cyt = st[t * 8 + 5];
            float areaT = st[t * 8 + 6];
            int cl = scls[t];

            bool inB = fminf(fminf(xc - tx0, yc - ty0), fminf(tx1 - xc, ty1 - yc)) > 0.f;
            bool inC = fmaxf(fabsf(xc - cxt), fabsf(yc - cyt)) < rad;

            float lx = fmaxf(tx0, px0), ly = fmaxf(ty0, py0);
            float rx = fminf(tx1, px1), ry = fminf(ty1, py1);
            float w = fmaxf(rx - lx, 0.f), h = fmaxf(ry - ly, 0.f);
            float inter = w * h;
            float uni = areaT + areaP - inter;
            float iou = inter / fmaxf(uni, 1e-9f);

            maxiou = fmaxf(maxiou, iou);
            anyB |= inB; anyC |= inC;

            float cost = (S - row[4 + cl]) + 3.0f * (-logf(iou + 1e-8f));
            if (!(inB && inC)) cost += 100000.0f;
            // (+1e9 * !in_box_anchor is identically +0.0f whenever best_t matters)
            if (cost < bestC) { bestC = cost; bestT = t; }   // first-min tie: jnp.argmin
        }

        iba = anyB || anyC;
        int gi = b * A + a;
        d_bestt[gi] = bestT;
        d_piou [gi] = maxiou;
        d_count[gi] = 0;
        d_mint [gi] = 0x7fffffff;
    }

    // warp-aggregated compaction append
    unsigned m = __ballot_sync(0xffffffffu, iba);
    if (m) {
        int leader = __ffs(m) - 1;
        int wbase = 0;
        if (lane == leader) wbase = atomicAdd(&d_cnt[b], __popc(m));
        wbase = __shfl_sync(0xffffffffu, wbase, leader);
        if (iba) {
            int pos = wbase + __popc(m & ((1u << lane) - 1u));
            d_gbox [b][pos] = make_float4(px0, py0, px1, py1);
            d_gmeta[b][pos] = make_float4(xc, yc, rad, __int_as_float(a));
            float* ctr = &d_gct[b][pos][0];
            for (int t = 0; t < T; t++) ctr[t] = S - row[4 + scls[t]];
        }
    }
}

// K2: warp per target, 8 targets per block (shared 32B sectors of ct rows +
// L1 reuse of candidate stream). Top-10 by iou (dyn_k) + top-10 by cost, then
// atomics for matching.
__global__ __launch_bounds__(256) void k2_target(
    const float* __restrict__ target, int A, int T)
{
    int b    = blockIdx.y;
    int warp = threadIdx.x >> 5;
    int lane = threadIdx.x & 31;
    int t    = blockIdx.x * 8 + warp;
    if (t >= T) return;                       // warp-uniform exit, no block syncs

    int N = d_cnt[b];
    const float* tg = target + ((size_t)b * T + t) * 5;
    float tx0 = tg[1], ty0 = tg[2], tx1 = tg[3], ty1 = tg[4];
    float cxt = 0.5f * (tx0 + tx1), cyt = 0.5f * (ty0 + ty1);
    float areaT = (tx1 - tx0) * (ty1 - ty0);

    float cv[KCAND]; int ci[KCAND]; float iv[KCAND];
    #pragma unroll
    for (int j = 0; j < KCAND; j++) { cv[j] = FLT_MAX; ci[j] = 0x7fffffff; iv[j] = -1.f; }

    for (int i = lane; i < N; i += 32) {
        float4 bx = d_gbox[b][i];
        float4 mt = d_gmeta[b][i];
        float  ct = d_gct[b][i][t];
        float xc = mt.x, yc = mt.y, rad = mt.z;
        int aidx = __float_as_int(mt.w);

        bool inB = fminf(fminf(xc - tx0, yc - ty0), fminf(tx1 - xc, ty1 - yc)) > 0.f;
        bool inC = fmaxf(fabsf(xc - cxt), fabsf(yc - cyt)) < rad;

        float lx = fmaxf(tx0, bx.x), ly = fmaxf(ty0, bx.y);
        float rx = fminf(tx1, bx.z), ry = fminf(ty1, bx.w);
        float w = fmaxf(rx - lx, 0.f), h = fmaxf(ry - ly, 0.f);
        float inter = w * h;
        float areaP = (bx.z - bx.x) * (bx.w - bx.y);
        float uni = areaT + areaP - inter;
        float iou = inter / fmaxf(uni, 1e-9f);

        float cost = ct + 3.0f * (-logf(iou + 1e-8f));
        if (!(inB && inC)) cost += 100000.0f;

        // iou top-10 (descending)
        if (iou > iv[KCAND - 1]) {
            float v = iou;
            #pragma unroll
            for (int j = KCAND - 1; j >= 0; j--) {
                if (j > 0 && iv[j - 1] < v) { iv[j] = iv[j - 1]; }
                else { iv[j] = v; break; }
            }
        }
        // cost top-10 (ascending, tie-break: lower original anchor idx)
        bool bet = (cost < cv[KCAND - 1]) ||
                   (cost == cv[KCAND - 1] && aidx < ci[KCAND - 1]);
        if (bet) {
            float c = cost; int id = aidx;
            #pragma unroll
            for (int j = KCAND - 1; j >= 0; j--) {
                bool shift = (j > 0) &&
                    ((c < cv[j - 1]) || (c == cv[j - 1] && id < ci[j - 1]));
                if (shift) { cv[j] = cv[j - 1]; ci[j] = ci[j - 1]; }
                else { cv[j] = c; ci[j] = id; break; }
            }
        }
    }

    // --- warp merge: iou top-10 sum -> dyn_k ---
    float sum = 0.f;
    #pragma unroll
    for (int r = 0; r < KCAND; r++) {
        float v = iv[0]; int wl = lane;
        #pragma unroll
        for (int off = 16; off; off >>= 1) {
            float ov = __shfl_xor_sync(0xffffffffu, v, off);
            int   ol = __shfl_xor_sync(0xffffffffu, wl, off);
            if (ov > v || (ov == v && ol < wl)) { v = ov; wl = ol; }
        }
        if (v > 0.f) sum += v;   // sums in descending order, like reference
        if (lane == wl) {
            #pragma unroll
            for (int j = 0; j < KCAND - 1; j++) iv[j] = iv[j + 1];
            iv[KCAND - 1] = -1.f;
        }
    }
    int dk = (int)sum;           // truncation, like .astype(int32)
    if (dk < 1) dk = 1;
    if (dk > KCAND) dk = KCAND;

    // --- warp merge: cost ascending, commit first dk ---
    #pragma unroll
    for (int r = 0; r < KCAND; r++) {
        float v = cv[0]; int id = ci[0]; int wl = lane;
        #pragma unroll
        for (int off = 16; off; off >>= 1) {
            float ov = __shfl_xor_sync(0xffffffffu, v, off);
            int   oi = __shfl_xor_sync(0xffffffffu, id, off);
            int   ol = __shfl_xor_sync(0xffffffffu, wl, off);
            if (ov < v || (ov == v && (oi < id || (oi == id && ol < wl)))) {
                v = ov; id = oi; wl = ol;
            }
        }
        if (lane == wl) {
            #pragma unroll
            for (int j = 0; j < KCAND - 1; j++) { cv[j] = cv[j + 1]; ci[j] = ci[j + 1]; }
            cv[KCAND - 1] = FLT_MAX; ci[KCAND - 1] = 0x7fffffff;
        }
        if (lane == 0 && r < dk && id != 0x7fffffff) {
            atomicAdd(&d_count[b * A + id], 1);
            atomicMin(&d_mint [b * A + id], t);
        }
    }
}

// K4: resolve matches and emit outputs (mm | box | obj | cls concatenated)
__global__ __launch_bounds__(256) void k4_final(
    const float* __restrict__ target, float* __restrict__ out,
    int A, int T, int B)
{
    int i = blockIdx.x * 256 + threadIdx.x;
    int BA = B * A;
    if (i >= BA) return;
    int b = i / A;
    int c = d_count[i];

    float mm = 0.f, b0 = 0, b1 = 0, b2 = 0, b3 = 0, obj = 0, clo = (float)NCLS;
    if (c > 0) {
        int t = (c == 1) ? d_mint[i] : d_bestt[i];
        const float* tg = target + ((size_t)b * T + t) * 5;
        mm = 1.f;
        clo = tg[0];
        b0 = tg[1]; b1 = tg[2]; b2 = tg[3]; b3 = tg[4];
        obj = d_piou[i];
    }
    out[i] = mm;
    float* ob = out + BA;
    ob[(size_t)i * 4 + 0] = b0;
    ob[(size_t)i * 4 + 1] = b1;
    ob[(size_t)i * 4 + 2] = b2;
    ob[(size_t)i * 4 + 3] = b3;
    out[(size_t)5 * BA + i] = obj;
    out[(size_t)6 * BA + i] = clo;
}

extern "C" void kernel_launch(void* const* d_in, const int* in_sizes, int n_in,
                              void* d_out, int out_size)
{
    const float* pred    = (const float*)d_in[0];
    const float* target  = (const float*)d_in[1];
    const float* grid    = (const float*)d_in[2];
    const float* stridem = (const float*)d_in[3];

    int A = in_sizes[3];
    int B = in_sizes[0] / (A * 84);
    int T = in_sizes[1] / (B * 5);

    k0_zero<<<1, 32>>>();

    dim3 g1((A + 127) / 128, B);
    k1_anchor<<<g1, 128>>>(pred, target, grid, stridem, A, T);

    dim3 g2((T + 7) / 8, B);
    k2_target<<<g2, 256>>>(target, A, T);

    int BA = B * A;
    k4_final<<<(BA + 255) / 256, 256>>>(target, (float*)d_out, A, T, B);
}

// round 2
// speedup vs baseline: 1.2418x; 1.2418x over previous
#include <cuda_runtime.h>
#include <math.h>
#include <float.h>

#define MAXB 16
#define MAXA 33600
#define MAXT 50
#define NCLS 80
#define KCAND 10
#define INV_LN2 1.4426950408889634f
#define PEN2 (100000.0f * 1.4426950408889634f)

// Scratch (static __device__ globals; ~131MB total)
__device__ int    d_cnt[MAXB];
__device__ float4 d_gbox [MAXB][MAXA];
__device__ float4 d_gmeta[MAXB][MAXA];
__device__ float  d_gct  [MAXB * MAXT * MAXA];   // [b][t][pos] transposed: coalesced
__device__ int    d_pos  [MAXB * MAXA];          // anchor -> compact pos (-1 if not iba)
__device__ int    d_count[MAXB * MAXA];          // indexed by compact pos
__device__ int    d_mint [MAXB * MAXA];

__global__ void k0_zero() {
    if (threadIdx.x < MAXB) d_cnt[threadIdx.x] = 0;
}

// K1: per-anchor. Computes S2 = log2(prod(1+e^z)) (softplus-sum in log2 domain),
// in_box_anchor flags, and compacts good anchors with transposed cls-cost rows.
// NO per-(a,t) log / iou here (deferred to K4 for the few matched anchors).
__global__ __launch_bounds__(128) void k1_anchor(
    const float* __restrict__ pred, const float* __restrict__ target,
    const float* __restrict__ grid, const float* __restrict__ stridem,
    int A, int T)
{
    __shared__ float sp[128 * 85];          // padded pred rows (85 coprime w/ 32 banks)
    __shared__ float st[MAXT * 8];          // x0,y0,x1,y1,cx,cy,(pad)
    __shared__ int   scls[MAXT];

    int b    = blockIdx.y;
    int base = blockIdx.x * 128;
    int nrows = min(128, A - base);

    const float* predb = pred + ((size_t)b * A + base) * 84;
    for (int i = threadIdx.x; i < nrows * 84; i += 128) {
        int r = i / 84;
        int c = i - r * 84;
        sp[r * 85 + c] = predb[i];
    }
    for (int i = threadIdx.x; i < T; i += 128) {
        const float* tg = target + ((size_t)b * T + i) * 5;
        float cl = tg[0], x0 = tg[1], y0 = tg[2], x1 = tg[3], y1 = tg[4];
        st[i * 8 + 0] = x0; st[i * 8 + 1] = y0;
        st[i * 8 + 2] = x1; st[i * 8 + 3] = y1;
        st[i * 8 + 4] = 0.5f * (x0 + x1);
        st[i * 8 + 5] = 0.5f * (y0 + y1);
        scls[i] = (int)cl;
    }
    __syncthreads();

    int tid  = threadIdx.x;
    int lane = tid & 31;
    bool alive = (tid < nrows);
    int a = base + tid;

    bool iba = false;
    float S2 = 0.f, px0 = 0, py0 = 0, px1 = 0, py1 = 0, xc = 0, yc = 0, rad = 0;
    const float* row = sp + tid * 85;

    if (alive) {
        float strv = stridem[a];
        xc  = (grid[2 * a]     + 0.5f) * strv;
        yc  = (grid[2 * a + 1] + 0.5f) * strv;
        rad = 2.5f * strv;
        px0 = row[0]; py0 = row[1]; px1 = row[2]; py1 = row[3];

        // S2 = log2( prod_c (1 + e^{z_c}) )  == softplus-sum / ln2
        float P = 1.f;
        int   E = 0;
        #pragma unroll 4
        for (int c = 0; c < NCLS; c++) {
            float e = __expf(row[4 + c]);
            P *= (1.f + e);
            if ((c & 3) == 3) {                 // exponent extraction renorm
                int bits = __float_as_int(P);
                E += ((bits >> 23) & 255) - 127;
                P = __int_as_float((bits & 0x007FFFFF) | 0x3F800000);
            }
        }
        S2 = (float)E + __log2f(P);

        bool anyB = false, anyC = false;
        for (int t = 0; t < T; t++) {
            float tx0 = st[t * 8 + 0], ty0 = st[t * 8 + 1];
            float tx1 = st[t * 8 + 2], ty1 = st[t * 8 + 3];
            float cxt = st[t * 8 + 4], cyt = st[t * 8 + 5];
            bool inB = fminf(fminf(xc - tx0, yc - ty0), fminf(tx1 - xc, ty1 - yc)) > 0.f;
            bool inC = fmaxf(fabsf(xc - cxt), fabsf(yc - cyt)) < rad;
            anyB |= inB; anyC |= inC;
        }
        iba = anyB || anyC;
        d_pos[b * A + a] = -1;
    }

    // warp-aggregated compaction append
    unsigned m = __ballot_sync(0xffffffffu, iba);
    if (m) {
        int leader = __ffs(m) - 1;
        int wbase = 0;
        if (lane == leader) wbase = atomicAdd(&d_cnt[b], __popc(m));
        wbase = __shfl_sync(0xffffffffu, wbase, leader);
        if (iba) {
            int pos = wbase + __popc(m & ((1u << lane) - 1u));
            d_pos  [b * A + a] = pos;
            d_gbox [b][pos] = make_float4(px0, py0, px1, py1);
            d_gmeta[b][pos] = make_float4(xc, yc, rad, __int_as_float(a));
            d_count[b * MAXA + pos] = 0;
            d_mint [b * MAXA + pos] = 0x7fffffff;
            // transposed cls-cost rows: coalesced across warp (pos consecutive)
            float* gct = d_gct + (size_t)b * MAXT * MAXA + pos;
            for (int t = 0; t < T; t++)
                gct[(size_t)t * MAXA] = S2 - row[4 + scls[t]] * INV_LN2;
        }
    }
}

// K2: warp per target, 8 targets per block. Scans compacted candidates.
// Top-10 by iou (dyn_k) + top-10 by log2-domain cost, then atomics.
__global__ __launch_bounds__(256) void k2_target(
    const float* __restrict__ target, int A, int T)
{
    int b    = blockIdx.y;
    int warp = threadIdx.x >> 5;
    int lane = threadIdx.x & 31;
    int t    = blockIdx.x * 8 + warp;
    if (t >= T) return;                       // warp-uniform exit, no block syncs

    int N = d_cnt[b];
    const float* tg = target + ((size_t)b * T + t) * 5;
    float tx0 = tg[1], ty0 = tg[2], tx1 = tg[3], ty1 = tg[4];
    float cxt = 0.5f * (tx0 + tx1), cyt = 0.5f * (ty0 + ty1);
    float areaT = (tx1 - tx0) * (ty1 - ty0);

    const float* gct = d_gct + ((size_t)b * MAXT + t) * MAXA;

    float cv[KCAND]; int ci[KCAND]; float iv[KCAND];
    #pragma unroll
    for (int j = 0; j < KCAND; j++) { cv[j] = FLT_MAX; ci[j] = 0x7fffffff; iv[j] = -1.f; }

    for (int i = lane; i < N; i += 32) {
        float4 bx = d_gbox[b][i];
        float4 mt = d_gmeta[b][i];
        float  ct = gct[i];                   // coalesced
        float xc = mt.x, yc = mt.y, rad = mt.z;
        int aidx = __float_as_int(mt.w);

        bool inB = fminf(fminf(xc - tx0, yc - ty0), fminf(tx1 - xc, ty1 - yc)) > 0.f;
        bool inC = fmaxf(fabsf(xc - cxt), fabsf(yc - cyt)) < rad;

        float lx = fmaxf(tx0, bx.x), ly = fmaxf(ty0, bx.y);
        float rx = fminf(tx1, bx.z), ry = fminf(ty1, bx.w);
        float w = fmaxf(rx - lx, 0.f), h = fmaxf(ry - ly, 0.f);
        float inter = w * h;
        float areaP = (bx.z - bx.x) * (bx.w - bx.y);
        float uni = areaT + areaP - inter;
        float iou = inter / fmaxf(uni, 1e-9f);

        float cost = ct - 3.0f * __log2f(iou + 1e-8f);   // log2-domain: same order
        if (!(inB && inC)) cost += PEN2;

        // iou top-10 (descending)
        if (iou > iv[KCAND - 1]) {
            float v = iou;
            #pragma unroll
            for (int j = KCAND - 1; j >= 0; j--) {
                if (j > 0 && iv[j - 1] < v) { iv[j] = iv[j - 1]; }
                else { iv[j] = v; break; }
            }
        }
        // cost top-10 (ascending, tie-break: lower original anchor idx)
        bool bet = (cost < cv[KCAND - 1]) ||
                   (cost == cv[KCAND - 1] && aidx < ci[KCAND - 1]);
        if (bet) {
            float c = cost; int id = aidx;
            #pragma unroll
            for (int j = KCAND - 1; j >= 0; j--) {
                bool shift = (j > 0) &&
                    ((c < cv[j - 1]) || (c == cv[j - 1] && id < ci[j - 1]));
                if (shift) { cv[j] = cv[j - 1]; ci[j] = ci[j - 1]; }
                else { cv[j] = c; ci[j] = id; break; }
            }
        }
    }

    // --- warp merge: iou top-10 sum -> dyn_k ---
    float sum = 0.f;
    #pragma unroll
    for (int r = 0; r < KCAND; r++) {
        float v = iv[0]; int wl = lane;
        #pragma unroll
        for (int off = 16; off; off >>= 1) {
            float ov = __shfl_xor_sync(0xffffffffu, v, off);
            int   ol = __shfl_xor_sync(0xffffffffu, wl, off);
            if (ov > v || (ov == v && ol < wl)) { v = ov; wl = ol; }
        }
        if (v > 0.f) sum += v;
        if (lane == wl) {
            #pragma unroll
            for (int j = 0; j < KCAND - 1; j++) iv[j] = iv[j + 1];
            iv[KCAND - 1] = -1.f;
        }
    }
    int dk = (int)sum;
    if (dk < 1) dk = 1;
    if (dk > KCAND) dk = KCAND;

    // --- warp merge: cost ascending, commit first dk (atomics on compact pos) ---
    #pragma unroll
    for (int r = 0; r < KCAND; r++) {
        float v = cv[0]; int id = ci[0]; int wl = lane;
        #pragma unroll
        for (int off = 16; off; off >>= 1) {
            float ov = __shfl_xor_sync(0xffffffffu, v, off);
            int   oi = __shfl_xor_sync(0xffffffffu, id, off);
            int   ol = __shfl_xor_sync(0xffffffffu, wl, off);
            if (ov < v || (ov == v && (oi < id || (oi == id && ol < wl)))) {
                v = ov; id = oi; wl = ol;
            }
        }
        int slot = -1;
        if (lane == wl) {
            slot = ci[0] == id && cv[0] == v ? 0 : 0;  // (placeholder, shift below)
            #pragma unroll
            for (int j = 0; j < KCAND - 1; j++) { cv[j] = cv[j + 1]; ci[j] = ci[j + 1]; }
            cv[KCAND - 1] = FLT_MAX; ci[KCAND - 1] = 0x7fffffff;
        }
        (void)slot;
        if (lane == 0 && r < dk && id != 0x7fffffff) {
            // id here is the ORIGINAL anchor index; atomics need compact pos:
            // recover via d_pos (id is guaranteed compacted since it came from gmeta)
            int p = d_pos[b * A + id];
            atomicAdd(&d_count[b * MAXA + p], 1);
            atomicMin(&d_mint [b * MAXA + p], t);
        }
    }
}

// K4: resolve matches (best_t / p_iou computed HERE, only for matched anchors)
// and emit outputs (mm | box | obj | cls concatenated).
__global__ __launch_bounds__(256) void k4_final(
    const float* __restrict__ target, float* __restrict__ out,
    int A, int T, int B)
{
    int i = blockIdx.x * 256 + threadIdx.x;
    int BA = B * A;
    if (i >= BA) return;
    int b = i / A;
    int pos = d_pos[i];
    int c = (pos >= 0) ? d_count[b * MAXA + pos] : 0;

    float mm = 0.f, b0 = 0, b1 = 0, b2 = 0, b3 = 0, obj = 0, clo = (float)NCLS;
    if (c > 0) {
        float4 bx = d_gbox[b][pos];
        float4 mt = d_gmeta[b][pos];
        float xc = mt.x, yc = mt.y, rad = mt.z;
        float areaP = (bx.z - bx.x) * (bx.w - bx.y);
        const float* gct = d_gct + (size_t)b * MAXT * MAXA + pos;

        float maxiou = 0.f;
        float bestC = FLT_MAX;
        int   bestT = 0;
        bool conflict = (c > 1);

        for (int t = 0; t < T; t++) {
            const float* tg = target + ((size_t)b * T + t) * 5;
            float tx0 = tg[1], ty0 = tg[2], tx1 = tg[3], ty1 = tg[4];
            float lx = fmaxf(tx0, bx.x), ly = fmaxf(ty0, bx.y);
            float rx = fminf(tx1, bx.z), ry = fminf(ty1, bx.w);
            float w = fmaxf(rx - lx, 0.f), h = fmaxf(ry - ly, 0.f);
            float inter = w * h;
            float areaT = (tx1 - tx0) * (ty1 - ty0);
            float uni = areaT + areaP - inter;
            float iou = inter / fmaxf(uni, 1e-9f);
            maxiou = fmaxf(maxiou, iou);

            if (conflict) {
                float cxt = 0.5f * (tx0 + tx1), cyt = 0.5f * (ty0 + ty1);
                bool inB = fminf(fminf(xc - tx0, yc - ty0), fminf(tx1 - xc, ty1 - yc)) > 0.f;
                bool inC = fmaxf(fabsf(xc - cxt), fabsf(yc - cyt)) < rad;
                float cost = gct[(size_t)t * MAXA] - 3.0f * __log2f(iou + 1e-8f);
                if (!(inB && inC)) cost += PEN2;
                if (cost < bestC) { bestC = cost; bestT = t; }   // first-min tie
            }
        }

        int t = conflict ? bestT : d_mint[b * MAXA + pos];
        const float* tg = target + ((size_t)b * T + t) * 5;
        mm = 1.f;
        clo = tg[0];
        b0 = tg[1]; b1 = tg[2]; b2 = tg[3]; b3 = tg[4];
        obj = maxiou;
    }
    out[i] = mm;
    float* ob = out + BA;
    ob[(size_t)i * 4 + 0] = b0;
    ob[(size_t)i * 4 + 1] = b1;
    ob[(size_t)i * 4 + 2] = b2;
    ob[(size_t)i * 4 + 3] = b3;
    out[(size_t)5 * BA + i] = obj;
    out[(size_t)6 * BA + i] = clo;
}

extern "C" void kernel_launch(void* const* d_in, const int* in_sizes, int n_in,
                              void* d_out, int out_size)
{
    const float* pred    = (const float*)d_in[0];
    const float* target  = (const float*)d_in[1];
    const float* grid    = (const float*)d_in[2];
    const float* stridem = (const float*)d_in[3];

    int A = in_sizes[3];
    int B = in_sizes[0] / (A * 84);
    int T = in_sizes[1] / (B * 5);

    k0_zero<<<1, 32>>>();

    dim3 g1((A + 127) / 128, B);
    k1_anchor<<<g1, 128>>>(pred, target, grid, stridem, A, T);

    dim3 g2((T + 7) / 8, B);
    k2_target<<<g2, 256>>>(target, A, T);

    int BA = B * A;
    k4_final<<<(BA + 255) / 256, 256>>>(target, (float*)d_out, A, T, B);
}

// round 3
// speedup vs baseline: 4.8009x; 3.8660x over previous
#include <cuda_runtime.h>
#include <math.h>
#include <float.h>

#define MAXB 16
#define MAXA 33600
#define MAXT 50
#define NCLS 80
#define KC 10
#define INV_LN2 1.4426950408889634f
#define PEN2 (100000.0f * 1.4426950408889634f)
#define BUFCAP 64
#define BUFTOT 80

// Scratch (static __device__ globals; ~131MB)
__device__ int    d_cnt[MAXB];
__device__ float4 d_gbox [MAXB][MAXA];
__device__ float4 d_gmeta[MAXB][MAXA];
__device__ float  d_gct  [MAXB * MAXT * MAXA];   // [b][t][pos] coalesced
__device__ int    d_pos  [MAXB * MAXA];
__device__ int    d_count[MAXB * MAXA];          // by original anchor id
__device__ int    d_mint [MAXB * MAXA];

__global__ void k0_zero() {
    if (threadIdx.x < MAXB) d_cnt[threadIdx.x] = 0;
}

// ---------- warp-parallel selection helpers (operate on smem) ----------
// top-10 smallest (v,id) lexicographic from buf[0..total); writes padded top list
__device__ __forceinline__ void sel_cost(float* bufv, int* bufi, int total,
                                         float* topv, int* topi, int lane)
{
    int rounds = min(KC, total);
    for (int r = 0; r < rounds; r++) {
        float v = FLT_MAX; int id = 0x7fffffff; int sl = 0;
        for (int s = lane; s < total; s += 32) {
            float vv = bufv[s]; int ii = bufi[s];
            if (vv < v || (vv == v && ii < id)) { v = vv; id = ii; sl = s; }
        }
        #pragma unroll
        for (int off = 16; off; off >>= 1) {
            float ov = __shfl_xor_sync(0xffffffffu, v, off);
            int   oi = __shfl_xor_sync(0xffffffffu, id, off);
            int   os = __shfl_xor_sync(0xffffffffu, sl, off);
            if (ov < v || (ov == v && oi < id)) { v = ov; id = oi; sl = os; }
        }
        if (lane == 0) { topv[r] = v; topi[r] = id; bufv[sl] = FLT_MAX; bufi[sl] = 0x7fffffff; }
        __syncwarp();
    }
    if (lane >= rounds && lane < KC) { topv[lane] = FLT_MAX; topi[lane] = 0x7fffffff; }
    __syncwarp();
}

// top-10 largest values from buf[0..total); padded with -1
__device__ __forceinline__ void sel_iou(float* bufv, int total, float* topv, int lane)
{
    int rounds = min(KC, total);
    for (int r = 0; r < rounds; r++) {
        float v = -1.f; int sl = 0;
        for (int s = lane; s < total; s += 32) {
            float vv = bufv[s];
            if (vv > v) { v = vv; sl = s; }
        }
        #pragma unroll
        for (int off = 16; off; off >>= 1) {
            float ov = __shfl_xor_sync(0xffffffffu, v, off);
            int   os = __shfl_xor_sync(0xffffffffu, sl, off);
            if (ov > v) { v = ov; sl = os; }
        }
        if (lane == 0) { topv[r] = v; bufv[sl] = -1.f; }
        __syncwarp();
    }
    if (lane >= rounds && lane < KC) topv[lane] = -1.f;
    __syncwarp();
}

// K1: per-anchor. S2 = softplus-sum/ln2, iba flags, compaction + transposed ct rows.
__global__ __launch_bounds__(128) void k1_anchor(
    const float* __restrict__ pred, const float* __restrict__ target,
    const float* __restrict__ grid, const float* __restrict__ stridem,
    int A, int T)
{
    __shared__ float sp[128 * 85];
    __shared__ float st[MAXT * 8];
    __shared__ int   scls[MAXT];

    int b    = blockIdx.y;
    int base = blockIdx.x * 128;
    int nrows = min(128, A - base);

    const float* predb = pred + ((size_t)b * A + base) * 84;
    for (int i = threadIdx.x; i < nrows * 84; i += 128) {
        int r = i / 84;
        int c = i - r * 84;
        sp[r * 85 + c] = predb[i];
    }
    for (int i = threadIdx.x; i < T; i += 128) {
        const float* tg = target + ((size_t)b * T + i) * 5;
        float cl = tg[0], x0 = tg[1], y0 = tg[2], x1 = tg[3], y1 = tg[4];
        st[i * 8 + 0] = x0; st[i * 8 + 1] = y0;
        st[i * 8 + 2] = x1; st[i * 8 + 3] = y1;
        st[i * 8 + 4] = 0.5f * (x0 + x1);
        st[i * 8 + 5] = 0.5f * (y0 + y1);
        scls[i] = (int)cl;
    }
    __syncthreads();

    int tid  = threadIdx.x;
    int lane = tid & 31;
    bool alive = (tid < nrows);
    int a = base + tid;

    bool iba = false;
    float S2 = 0.f, px0 = 0, py0 = 0, px1 = 0, py1 = 0, xc = 0, yc = 0, rad = 0;
    const float* row = sp + tid * 85;

    if (alive) {
        float strv = stridem[a];
        xc  = (grid[2 * a]     + 0.5f) * strv;
        yc  = (grid[2 * a + 1] + 0.5f) * strv;
        rad = 2.5f * strv;
        px0 = row[0]; py0 = row[1]; px1 = row[2]; py1 = row[3];

        // S2 = log2( prod_c (1 + e^{z_c}) )
        float P = 1.f;
        int   E = 0;
        #pragma unroll 4
        for (int c = 0; c < NCLS; c++) {
            float e = __expf(row[4 + c]);
            P *= (1.f + e);
            if ((c & 3) == 3) {
                int bits = __float_as_int(P);
                E += ((bits >> 23) & 255) - 127;
                P = __int_as_float((bits & 0x007FFFFF) | 0x3F800000);
            }
        }
        S2 = (float)E + __log2f(P);

        bool anyB = false, anyC = false;
        for (int t = 0; t < T; t++) {
            float tx0 = st[t * 8 + 0], ty0 = st[t * 8 + 1];
            float tx1 = st[t * 8 + 2], ty1 = st[t * 8 + 3];
            float cxt = st[t * 8 + 4], cyt = st[t * 8 + 5];
            bool inB = fminf(fminf(xc - tx0, yc - ty0), fminf(tx1 - xc, ty1 - yc)) > 0.f;
            bool inC = fmaxf(fabsf(xc - cxt), fabsf(yc - cyt)) < rad;
            anyB |= inB; anyC |= inC;
        }
        iba = anyB || anyC;
        int gi = b * A + a;
        d_pos  [gi] = -1;
        d_count[gi] = 0;
        d_mint [gi] = 0x7fffffff;
    }

    unsigned m = __ballot_sync(0xffffffffu, iba);
    if (m) {
        int leader = __ffs(m) - 1;
        int wbase = 0;
        if (lane == leader) wbase = atomicAdd(&d_cnt[b], __popc(m));
        wbase = __shfl_sync(0xffffffffu, wbase, leader);
        if (iba) {
            int pos = wbase + __popc(m & ((1u << lane) - 1u));
            d_pos  [b * A + a] = pos;
            d_gbox [b][pos] = make_float4(px0, py0, px1, py1);
            d_gmeta[b][pos] = make_float4(xc, yc, rad, __int_as_float(a));
            float* gct = d_gct + (size_t)b * MAXT * MAXA + pos;
            for (int t = 0; t < T; t++)
                gct[(size_t)t * MAXA] = S2 - row[4 + scls[t]] * INV_LN2;
        }
    }
}

// K2: block per (target, image). 256 threads scan candidates with
// threshold-filtered top-k (no per-lane arrays), then in-block merge + atomics.
__global__ __launch_bounds__(256) void k2_target(
    const float* __restrict__ target, int A, int T)
{
    __shared__ float sbcv[8][BUFTOT]; __shared__ int sbci[8][BUFTOT];
    __shared__ float sbiv[8][BUFTOT];
    __shared__ float stcv[8][KC];     __shared__ int stci[8][KC];
    __shared__ float stiv[8][KC];
    __shared__ float smcv[KC];        __shared__ int smci[KC];
    __shared__ float smiv[KC];
    __shared__ int sdk;

    int b = blockIdx.y;
    int t = blockIdx.x;
    int w = threadIdx.x >> 5, lane = threadIdx.x & 31;
    int N = d_cnt[b];

    // init per-warp top lists to sentinels
    if (lane < KC) {
        stcv[w][lane] = FLT_MAX; stci[w][lane] = 0x7fffffff;
        stiv[w][lane] = -1.f;
    }
    __syncwarp();

    const float* tg = target + ((size_t)b * T + t) * 5;
    float tx0 = tg[1], ty0 = tg[2], tx1 = tg[3], ty1 = tg[4];
    float cxt = 0.5f * (tx0 + tx1), cyt = 0.5f * (ty0 + ty1);
    float areaT = (tx1 - tx0) * (ty1 - ty0);
    const float* gct = d_gct + ((size_t)b * MAXT + t) * MAXA;

    float thv = FLT_MAX; int thi = 0x7fffffff; int nbc = 0;  // cost threshold/buffer
    float thI = 0.f;                             int nbi = 0; // iou threshold/buffer

    for (int basei = 0; basei < N; basei += 256) {
        int i = basei + threadIdx.x;
        bool valid = i < N;
        int ii = valid ? i : (N - 1);
        float4 bx = d_gbox[b][ii];
        float4 mt = d_gmeta[b][ii];
        float  ct = gct[ii];
        float xc = mt.x, yc = mt.y, rad = mt.z;
        int aidx = __float_as_int(mt.w);

        bool inB = fminf(fminf(xc - tx0, yc - ty0), fminf(tx1 - xc, ty1 - yc)) > 0.f;
        bool inC = fmaxf(fabsf(xc - cxt), fabsf(yc - cyt)) < rad;

        float lx = fmaxf(tx0, bx.x), ly = fmaxf(ty0, bx.y);
        float rx = fminf(tx1, bx.z), ry = fminf(ty1, bx.w);
        float ww = fmaxf(rx - lx, 0.f), hh = fmaxf(ry - ly, 0.f);
        float inter = ww * hh;
        float areaP = (bx.z - bx.x) * (bx.w - bx.y);
        float uni = areaT + areaP - inter;
        float iou = inter / fmaxf(uni, 1e-9f);

        float cost = ct - 3.0f * __log2f(iou + 1e-8f);
        if (!(inB && inC)) cost += PEN2;

        // ---- iou top-k (values only, descending) ----
        bool pI = valid && (iou > thI);
        unsigned mi = __ballot_sync(0xffffffffu, pI);
        if (mi) {
            int cnt = __popc(mi);
            if (nbi + cnt > BUFCAP) {
                if (lane < KC) sbiv[w][nbi + lane] = stiv[w][lane];
                __syncwarp();
                sel_iou(sbiv[w], nbi + KC, stiv[w], lane);
                thI = fmaxf(stiv[w][KC - 1], 0.f);
                nbi = 0;
                pI = valid && (iou > thI);
                mi = __ballot_sync(0xffffffffu, pI);
                cnt = __popc(mi);
            }
            if (pI) sbiv[w][nbi + __popc(mi & ((1u << lane) - 1u))] = iou;
            nbi += cnt;
        }
        // ---- cost top-k ((cost,idx) lexicographic ascending) ----
        bool pC = valid && (cost < thv || (cost == thv && aidx < thi));
        unsigned mc = __ballot_sync(0xffffffffu, pC);
        if (mc) {
            int cnt = __popc(mc);
            if (nbc + cnt > BUFCAP) {
                if (lane < KC) { sbcv[w][nbc + lane] = stcv[w][lane]; sbci[w][nbc + lane] = stci[w][lane]; }
                __syncwarp();
                sel_cost(sbcv[w], sbci[w], nbc + KC, stcv[w], stci[w], lane);
                thv = stcv[w][KC - 1]; thi = stci[w][KC - 1];
                nbc = 0;
                pC = valid && (cost < thv || (cost == thv && aidx < thi));
                mc = __ballot_sync(0xffffffffu, pC);
                cnt = __popc(mc);
            }
            if (pC) {
                int slot = nbc + __popc(mc & ((1u << lane) - 1u));
                sbcv[w][slot] = cost; sbci[w][slot] = aidx;
            }
            nbc += cnt;
        }
    }

    // final per-warp flushes
    if (lane < KC) sbiv[w][nbi + lane] = stiv[w][lane];
    __syncwarp();
    sel_iou(sbiv[w], nbi + KC, stiv[w], lane);
    if (lane < KC) { sbcv[w][nbc + lane] = stcv[w][lane]; sbci[w][nbc + lane] = stci[w][lane]; }
    __syncwarp();
    sel_cost(sbcv[w], sbci[w], nbc + KC, stcv[w], stci[w], lane);
    __syncthreads();

    // cross-warp merges (warp0: cost over 8*10; warp1: iou + dyn_k)
    if (w == 0) {
        sel_cost(&stcv[0][0], &stci[0][0], 8 * KC, smcv, smci, lane);
    } else if (w == 1) {
        sel_iou(&stiv[0][0], 8 * KC, smiv, lane);
        if (lane == 0) {
            float s = 0.f;
            #pragma unroll
            for (int r = 0; r < KC; r++) { float v = smiv[r]; if (v > 0.f) s += v; }
            int dk = (int)s;
            sdk = max(1, min(KC, dk));
        }
    }
    __syncthreads();

    if (threadIdx.x < KC) {
        int r = threadIdx.x;
        int id = smci[r];
        if (r < sdk && id != 0x7fffffff) {
            atomicAdd(&d_count[b * A + id], 1);
            atomicMin(&d_mint [b * A + id], t);
        }
    }
}

// K4: resolve + emit (mm | box | obj | cls concatenated)
__global__ __launch_bounds__(256) void k4_final(
    const float* __restrict__ target, float* __restrict__ out,
    int A, int T, int B)
{
    __shared__ float st[MAXT * 5];
    int b = blockIdx.y;
    for (int j = threadIdx.x; j < T * 5; j += 256)
        st[j] = target[(size_t)b * T * 5 + j];
    __syncthreads();

    int a = blockIdx.x * 256 + threadIdx.x;
    if (a >= A) return;
    int BA = B * A;
    int i = b * A + a;
    int c = d_count[i];

    float mm = 0.f, b0 = 0, b1 = 0, b2 = 0, b3 = 0, obj = 0, clo = (float)NCLS;
    if (c > 0) {
        int pos = d_pos[i];
        float4 bx = d_gbox[b][pos];
        float4 mt = d_gmeta[b][pos];
        float xc = mt.x, yc = mt.y, rad = mt.z;
        float areaP = (bx.z - bx.x) * (bx.w - bx.y);
        const float* gct = d_gct + (size_t)b * MAXT * MAXA + pos;

        float maxiou = 0.f;
        float bestC = FLT_MAX;
        int   bestT = 0;
        bool conflict = (c > 1);

        for (int t = 0; t < T; t++) {
            float tx0 = st[t * 5 + 1], ty0 = st[t * 5 + 2];
            float tx1 = st[t * 5 + 3], ty1 = st[t * 5 + 4];
            float lx = fmaxf(tx0, bx.x), ly = fmaxf(ty0, bx.y);
            float rx = fminf(tx1, bx.z), ry = fminf(ty1, bx.w);
            float w = fmaxf(rx - lx, 0.f), h = fmaxf(ry - ly, 0.f);
            float inter = w * h;
            float areaT = (tx1 - tx0) * (ty1 - ty0);
            float uni = areaT + areaP - inter;
            float iou = inter / fmaxf(uni, 1e-9f);
            maxiou = fmaxf(maxiou, iou);

            if (conflict) {
                float cxt = 0.5f * (tx0 + tx1), cyt = 0.5f * (ty0 + ty1);
                bool inB = fminf(fminf(xc - tx0, yc - ty0), fminf(tx1 - xc, ty1 - yc)) > 0.f;
                bool inC = fmaxf(fabsf(xc - cxt), fabsf(yc - cyt)) < rad;
                float cost = gct[(size_t)t * MAXA] - 3.0f * __log2f(iou + 1e-8f);
                if (!(inB && inC)) cost += PEN2;
                if (cost < bestC) { bestC = cost; bestT = t; }
            }
        }

        int tt = conflict ? bestT : d_mint[i];
        mm = 1.f;
        clo = st[tt * 5 + 0];
        b0 = st[tt * 5 + 1]; b1 = st[tt * 5 + 2];
        b2 = st[tt * 5 + 3]; b3 = st[tt * 5 + 4];
        obj = maxiou;
    }
    out[i] = mm;
    ((float4*)(out + BA))[i] = make_float4(b0, b1, b2, b3);
    out[(size_t)5 * BA + i] = obj;
    out[(size_t)6 * BA + i] = clo;
}

extern "C" void kernel_launch(void* const* d_in, const int* in_sizes, int n_in,
                              void* d_out, int out_size)
{
    const float* pred    = (const float*)d_in[0];
    const float* target  = (const float*)d_in[1];
    const float* grid    = (const float*)d_in[2];
    const float* stridem = (const float*)d_in[3];

    int A = in_sizes[3];
    int B = in_sizes[0] / (A * 84);
    int T = in_sizes[1] / (B * 5);

    k0_zero<<<1, 32>>>();

    dim3 g1((A + 127) / 128, B);
    k1_anchor<<<g1, 128>>>(pred, target, grid, stridem, A, T);

    dim3 g2(T, B);
    k2_target<<<g2, 256>>>(target, A, T);

    dim3 g4((A + 255) / 256, B);
    k4_final<<<g4, 256>>>(target, (float*)d_out, A, T, B);
}